// round 3
// baseline (speedup 1.0000x reference)
#include <cuda_runtime.h>
#include <math.h>

// Problem constants (fixed shapes from reference setup_inputs)
#define B_  8
#define S_  8192
#define D_  512
#define H_  256
#define M_  (B_*S_)        // 65536 rows

// GEMM tiling
#define MT  128            // rows per CTA
#define HT  32             // h-channels per CTA (x3 gates = 96 cols)
#define NCOL (3*HT)        // 96
#define KT  16
#define NK  (D_/KT)        // 32

// Scan chunking
#define LCH 128
#define NCH (S_/LCH)       // 64

// Scratch (device globals — allocation-free per harness rules)
__device__ float g_a[(size_t)M_*H_];          // forget gate f' per (m,h)
__device__ float g_c[(size_t)M_*H_];          // i' * g(h~) per (m,h)
__device__ float g_Ae[(size_t)B_*NCH*H_];     // per-chunk product of a
__device__ float g_Be[(size_t)B_*NCH*H_];     // per-chunk affine offset
__device__ float g_h0[(size_t)B_*NCH*H_];     // h at start of each chunk

__device__ __forceinline__ float softplus_f(float z) {
    // stable: max(z,0) + log1p(exp(-|z|))
    return fmaxf(z, 0.0f) + log1pf(expf(-fabsf(z)));
}

// ---------------------------------------------------------------------------
// Kernel 1: fused GEMM + gate epilogue.
// Computes y = x @ W^T for the 3 gate blocks of a 32-wide h tile, then:
//   diff = softplus(-f) - softplus(-i)
//   a = sigmoid(-diff)            (forget gate, == exp(log_f))
//   c = sigmoid(diff) * g(h~)     (input contribution, == exp(log_i + log_g))
// ---------------------------------------------------------------------------
__global__ __launch_bounds__(256) void k_gemm_gates(
    const float* __restrict__ x, const float* __restrict__ W)
{
    __shared__ float As[2][MT][KT + 1];      // [buf][row][k]
    __shared__ float Bs[2][NCOL][KT + 1];    // [buf][col][k]  col = gate*32 + hl

    const int tid = threadIdx.x;
    const int tx = tid & 15;
    const int ty = tid >> 4;
    const int m0 = blockIdx.x * MT;
    const int h0 = blockIdx.y * HT;

    float acc[8][6];
#pragma unroll
    for (int i = 0; i < 8; i++)
#pragma unroll
        for (int j = 0; j < 6; j++) acc[i][j] = 0.0f;

    // ---- global load assignments ----
    // A tile: 128 rows x 16 k = 512 float4; each thread: ids tid and tid+256.
    const int arow0 = tid >> 2;
    const int arow1 = (tid + 256) >> 2;
    const int akq   = tid & 3;               // which float4 within the 16-k row
    // B tile: 96 rows x 16 k = 384 float4; ids tid (all) and tid+256 (tid<128).
    const int bc0   = tid >> 2;              // col 0..63
    const int bc1   = (tid + 256) >> 2;      // col 64..95 (tid<128)
    const int wrow0 = (bc0 >> 5) * H_ + h0 + (bc0 & 31);
    const int wrow1 = (bc1 >> 5) * H_ + h0 + (bc1 & 31);

    float4 ra0, ra1, rb0, rb1;
    rb1 = make_float4(0.f, 0.f, 0.f, 0.f);

    auto gload = [&](int kt) {
        const int k0 = kt * KT + akq * 4;
        ra0 = *(const float4*)&x[(size_t)(m0 + arow0) * D_ + k0];
        ra1 = *(const float4*)&x[(size_t)(m0 + arow1) * D_ + k0];
        rb0 = *(const float4*)&W[(size_t)wrow0 * D_ + k0];
        if (tid < 128)
            rb1 = *(const float4*)&W[(size_t)wrow1 * D_ + k0];
    };
    auto sstore = [&](int buf) {
        const int kb = akq * 4;
        As[buf][arow0][kb + 0] = ra0.x; As[buf][arow0][kb + 1] = ra0.y;
        As[buf][arow0][kb + 2] = ra0.z; As[buf][arow0][kb + 3] = ra0.w;
        As[buf][arow1][kb + 0] = ra1.x; As[buf][arow1][kb + 1] = ra1.y;
        As[buf][arow1][kb + 2] = ra1.z; As[buf][arow1][kb + 3] = ra1.w;
        Bs[buf][bc0][kb + 0] = rb0.x; Bs[buf][bc0][kb + 1] = rb0.y;
        Bs[buf][bc0][kb + 2] = rb0.z; Bs[buf][bc0][kb + 3] = rb0.w;
        if (tid < 128) {
            Bs[buf][bc1][kb + 0] = rb1.x; Bs[buf][bc1][kb + 1] = rb1.y;
            Bs[buf][bc1][kb + 2] = rb1.z; Bs[buf][bc1][kb + 3] = rb1.w;
        }
    };

    gload(0);
    sstore(0);
    __syncthreads();

    for (int kt = 0; kt < NK; kt++) {
        const int cur = kt & 1;
        if (kt + 1 < NK) gload(kt + 1);
#pragma unroll
        for (int k = 0; k < KT; k++) {
            float av[8], bv[6];
#pragma unroll
            for (int i = 0; i < 8; i++) av[i] = As[cur][ty + 16 * i][k];
#pragma unroll
            for (int j = 0; j < 6; j++) bv[j] = Bs[cur][tx + 16 * j][k];
#pragma unroll
            for (int i = 0; i < 8; i++)
#pragma unroll
                for (int j = 0; j < 6; j++)
                    acc[i][j] = fmaf(av[i], bv[j], acc[i][j]);
        }
        if (kt + 1 < NK) {
            __syncthreads();
            sstore(cur ^ 1);
            __syncthreads();
        }
    }

    // ---- fused gate epilogue ----
    // col mapping: j=0,1 -> f (hl = tx, tx+16); j=2,3 -> i; j=4,5 -> h~
#pragma unroll
    for (int i = 0; i < 8; i++) {
        const int m = m0 + ty + 16 * i;
#pragma unroll
        for (int p = 0; p < 2; p++) {
            const float f  = acc[i][p];
            const float iv = acc[i][2 + p];
            const float hv = acc[i][4 + p];

            const float diff = softplus_f(-f) - softplus_f(-iv);
            const float fp = 1.0f / (1.0f + expf(diff));    // sigmoid(-diff)
            const float ip = 1.0f / (1.0f + expf(-diff));   // sigmoid(diff)
            const float gv = (hv >= 0.0f) ? (hv + 0.5f)
                                          : 1.0f / (1.0f + expf(-hv));
            const int hidx = h0 + tx + 16 * p;
            const size_t o = (size_t)m * H_ + hidx;
            g_a[o] = fp;
            g_c[o] = ip * gv;
        }
    }
}

// ---------------------------------------------------------------------------
// Kernel 2: per-chunk affine reduction.  For each (b, h, chunk):
//   h_end = A * h_start + B  with  A = prod(a_t), B = scan of c with h=0.
// One block per (b,chunk); 256 threads cover all h — fully coalesced.
// ---------------------------------------------------------------------------
__global__ __launch_bounds__(256) void k_chunk()
{
    const int bc = blockIdx.x;               // b*NCH + ch
    const int b  = bc / NCH;
    const int ch = bc % NCH;
    const int h  = threadIdx.x;
    size_t base = ((size_t)b * S_ + (size_t)ch * LCH) * H_ + h;

    float A = 1.0f, Bv = 0.0f;
#pragma unroll 8
    for (int t = 0; t < LCH; t++) {
        const float a = g_a[base + (size_t)t * H_];
        const float c = g_c[base + (size_t)t * H_];
        Bv = fmaf(a, Bv, c);
        A *= a;
    }
    g_Ae[(size_t)bc * H_ + h] = A;
    g_Be[(size_t)bc * H_ + h] = Bv;
}

// ---------------------------------------------------------------------------
// Kernel 3: cross-chunk chain (tiny): sequential over 64 chunks per channel.
// h_start(chunk 0) = g(h_prev).
// ---------------------------------------------------------------------------
__global__ void k_chain(const float* __restrict__ h_prev)
{
    const int idx = blockIdx.x * blockDim.x + threadIdx.x;   // < B_*H_
    const int b = idx / H_;
    const int h = idx % H_;

    const float z = h_prev[idx];
    float run = (z >= 0.0f) ? (z + 0.5f) : 1.0f / (1.0f + expf(-z));

    for (int k = 0; k < NCH; k++) {
        const size_t o = ((size_t)(b * NCH + k)) * H_ + h;
        g_h0[o] = run;
        run = fmaf(g_Ae[o], run, g_Be[o]);
    }
}

// ---------------------------------------------------------------------------
// Kernel 4: replay each chunk with its true h_start, writing outputs.
// ---------------------------------------------------------------------------
__global__ __launch_bounds__(256) void k_out(float* __restrict__ out)
{
    const int bc = blockIdx.x;
    const int b  = bc / NCH;
    const int ch = bc % NCH;
    const int h  = threadIdx.x;
    size_t base = ((size_t)b * S_ + (size_t)ch * LCH) * H_ + h;

    float hc = g_h0[(size_t)bc * H_ + h];
#pragma unroll 4
    for (int t = 0; t < LCH; t++) {
        const float a = g_a[base + (size_t)t * H_];
        const float c = g_c[base + (size_t)t * H_];
        hc = fmaf(a, hc, c);
        out[base + (size_t)t * H_] = hc;
    }
}

// ---------------------------------------------------------------------------
extern "C" void kernel_launch(void* const* d_in, const int* in_sizes, int n_in,
                              void* d_out, int out_size)
{
    const float* x  = nullptr;
    const float* hp = nullptr;
    const float* Wp = nullptr;
    for (int i = 0; i < n_in; i++) {
        if      (in_sizes[i] == M_ * D_)      x  = (const float*)d_in[i];
        else if (in_sizes[i] == B_ * H_)      hp = (const float*)d_in[i];
        else if (in_sizes[i] == 3 * H_ * D_)  Wp = (const float*)d_in[i];
    }
    float* out = (float*)d_out;

    dim3 g1(M_ / MT, H_ / HT);          // (512, 8)
    k_gemm_gates<<<g1, 256>>>(x, Wp);
    k_chunk<<<B_ * NCH, 256>>>();
    k_chain<<<(B_ * H_) / 256, 256>>>(hp);
    k_out<<<B_ * NCH, 256>>>(out);
}

// round 5
// speedup vs baseline: 2.2439x; 2.2439x over previous
#include <cuda_runtime.h>
#include <cuda_bf16.h>
#include <math.h>
#include <stdint.h>

// ---------------- problem constants ----------------
#define B_  8
#define S_  8192
#define D_  512
#define H_  256
#define M_  (B_*S_)            // 65536 rows
#define N3H (3*H_)             // 768

// ---------------- GEMM tiling (mma.sync path) ----------------
#define MT   128               // m rows per CTA
#define CH   64                // channels per CTA
#define NT   192               // cols per CTA footprint = 3 gates x 64 ch
#define NTILES 4               // 256 / 64
#define KS   64                // k per SMEM stage (64 bf16 = 128 B rows, SW128)
#define NKS  (D_/KS)           // 8
#define A_BYTES (MT*128)       // 16384 (one of hi/lo)
#define B_BYTES (NT*128)       // 24576
#define STAGE_BYTES (2*A_BYTES + 2*B_BYTES)   // 81920
#define SMEM_DYN (2*STAGE_BYTES)              // 163840

// scan chunking
#define LCH 128
#define NCH (S_/LCH)           // 64

// ---------------- device scratch ----------------
__device__ __nv_bfloat16 g_xh[(size_t)M_*D_];
__device__ __nv_bfloat16 g_xl[(size_t)M_*D_];
__device__ __nv_bfloat16 g_wh[(size_t)N3H*D_];   // permuted: [nt][192][512]
__device__ __nv_bfloat16 g_wl[(size_t)N3H*D_];
__device__ float g_a[(size_t)M_*H_];
__device__ float g_c[(size_t)M_*H_];
__device__ float g_Ae[(size_t)B_*NCH*H_];
__device__ float g_Be[(size_t)B_*NCH*H_];
__device__ float g_h0[(size_t)B_*NCH*H_];

// ---------------- PTX helpers ----------------
__device__ __forceinline__ uint32_t smem_u32(const void* p) {
    uint32_t a;
    asm("{ .reg .u64 t; cvta.to.shared.u64 t, %1; cvt.u32.u64 %0, t; }" : "=r"(a) : "l"(p));
    return a;
}
#define CP16(dst, src) asm volatile("cp.async.cg.shared.global [%0], [%1], 16;" :: "r"(dst), "l"(src) : "memory")
#define CP_COMMIT()    asm volatile("cp.async.commit_group;" ::: "memory")
#define CP_WAIT1()     asm volatile("cp.async.wait_group 1;" ::: "memory")
#define CP_WAIT0()     asm volatile("cp.async.wait_group 0;" ::: "memory")
#define SWZ(o) ((o) ^ (((o) >> 3) & 0x70))

__device__ __forceinline__ void ldsm4(uint32_t* r, uint32_t addr) {
    asm volatile("ldmatrix.sync.aligned.m8n8.x4.shared.b16 {%0,%1,%2,%3}, [%4];"
                 : "=r"(r[0]), "=r"(r[1]), "=r"(r[2]), "=r"(r[3]) : "r"(addr));
}
__device__ __forceinline__ void mma16816(float* d, const uint32_t* a,
                                         uint32_t b0, uint32_t b1) {
    asm volatile("mma.sync.aligned.m16n8k16.row.col.f32.bf16.bf16.f32 "
                 "{%0,%1,%2,%3}, {%4,%5,%6,%7}, {%8,%9}, {%0,%1,%2,%3};"
                 : "+f"(d[0]), "+f"(d[1]), "+f"(d[2]), "+f"(d[3])
                 : "r"(a[0]), "r"(a[1]), "r"(a[2]), "r"(a[3]), "r"(b0), "r"(b1));
}

__device__ __forceinline__ float softplus_f(float z) {
    return fmaxf(z, 0.0f) + log1pf(expf(-fabsf(z)));
}

// ---------------------------------------------------------------------------
// fp32 -> bf16 hi/lo split conversions
// ---------------------------------------------------------------------------
__global__ __launch_bounds__(256) void k_conv_x(const float* __restrict__ x)
{
    size_t i = ((size_t)blockIdx.x * blockDim.x + threadIdx.x) * 4;
    float4 v = *(const float4*)&x[i];
    __nv_bfloat16 hx = __float2bfloat16(v.x), hy = __float2bfloat16(v.y);
    __nv_bfloat16 hz = __float2bfloat16(v.z), hw = __float2bfloat16(v.w);
    g_xh[i] = hx; g_xh[i+1] = hy; g_xh[i+2] = hz; g_xh[i+3] = hw;
    g_xl[i]   = __float2bfloat16(v.x - __bfloat162float(hx));
    g_xl[i+1] = __float2bfloat16(v.y - __bfloat162float(hy));
    g_xl[i+2] = __float2bfloat16(v.z - __bfloat162float(hz));
    g_xl[i+3] = __float2bfloat16(v.w - __bfloat162float(hw));
}

__global__ __launch_bounds__(256) void k_conv_w(const float* __restrict__ W)
{
    size_t i = ((size_t)blockIdx.x * blockDim.x + threadIdx.x) * 4;
    int r = (int)(i / D_);                 // src row 0..767
    int k = (int)(i % D_);
    int gate = r / H_, ch = r % H_;
    int ntv = ch / CH;
    size_t dst = ((size_t)(ntv * NT + gate * CH + (ch % CH))) * D_ + k;
    float4 v = *(const float4*)&W[i];
    __nv_bfloat16 hx = __float2bfloat16(v.x), hy = __float2bfloat16(v.y);
    __nv_bfloat16 hz = __float2bfloat16(v.z), hw = __float2bfloat16(v.w);
    g_wh[dst] = hx; g_wh[dst+1] = hy; g_wh[dst+2] = hz; g_wh[dst+3] = hw;
    g_wl[dst]   = __float2bfloat16(v.x - __bfloat162float(hx));
    g_wl[dst+1] = __float2bfloat16(v.y - __bfloat162float(hy));
    g_wl[dst+2] = __float2bfloat16(v.z - __bfloat162float(hz));
    g_wl[dst+3] = __float2bfloat16(v.w - __bfloat162float(hw));
}

// ---------------------------------------------------------------------------
// mma.sync bf16 GEMM + fused gate epilogue.
// grid = (NTILES, M_/MT) = (4, 512); 256 threads (8 warps).
// Warp w: rows [warp_m*32, +32), channels [warp_c*32, +32), all 3 gates.
// ---------------------------------------------------------------------------
__global__ __launch_bounds__(256, 1) void k_gemm_mma()
{
    extern __shared__ char dynsmem[];
    const uint32_t sb = smem_u32(dynsmem);

    const int tid  = threadIdx.x;
    const int warp = tid >> 5;
    const int lane = tid & 31;
    const int warp_m = warp & 3;           // 0..3
    const int warp_c = warp >> 2;          // 0..1
    const int nt = blockIdx.x;
    const int m0 = blockIdx.y * MT;
    const int r0 = nt * NT;                // row base in permuted W

    // acc[gate][mfrag][nfrag][4]
    float acc[3][2][4][4];
#pragma unroll
    for (int g = 0; g < 3; g++)
#pragma unroll
        for (int mf = 0; mf < 2; mf++)
#pragma unroll
            for (int nf = 0; nf < 4; nf++)
#pragma unroll
                for (int e = 0; e < 4; e++) acc[g][mf][nf][e] = 0.0f;

    // ---- cooperative loader ----
    auto prefetch = [&](int ks) {
        const int st = ks & 1;
        const uint32_t ah = sb + st * STAGE_BYTES;
        const uint32_t al = ah + A_BYTES;
        const uint32_t bh = ah + 2 * A_BYTES;
        const uint32_t bl = bh + B_BYTES;
        const int kb = ks * KS;            // bf16 element base
#pragma unroll
        for (int it = 0; it < 4; it++) {   // A: 128 rows x 8 chunks = 1024
            int id = it * 256 + tid, row = id >> 3, cq = id & 7;
            uint32_t d = SWZ((uint32_t)(row * 128 + cq * 16));
            size_t so = (size_t)(m0 + row) * D_ + kb + cq * 8;
            CP16(ah + d, (const void*)(g_xh + so));
            CP16(al + d, (const void*)(g_xl + so));
        }
#pragma unroll
        for (int it = 0; it < 6; it++) {   // B: 192 rows x 8 chunks = 1536
            int id = it * 256 + tid, row = id >> 3, cq = id & 7;
            uint32_t d = SWZ((uint32_t)(row * 128 + cq * 16));
            size_t so = (size_t)(r0 + row) * D_ + kb + cq * 8;
            CP16(bh + d, (const void*)(g_wh + so));
            CP16(bl + d, (const void*)(g_wl + so));
        }
        CP_COMMIT();
    };

    prefetch(0);

    const int arow = warp_m * 32 + (lane & 15);     // + mf*16
    const int ahalf = (lane >> 4) * 16;             // 16B k-half select
    const int brow = warp_c * 32 + (lane & 15);     // + gate*64 (+16 for second x4)

    for (int ks = 0; ks < NKS; ks++) {
        if (ks + 1 < NKS) { prefetch(ks + 1); CP_WAIT1(); }
        else             { CP_WAIT0(); }
        __syncthreads();

        const int st = ks & 1;
        const uint32_t ah_b = sb + st * STAGE_BYTES;
        const uint32_t al_b = ah_b + A_BYTES;
        const uint32_t bh_b = ah_b + 2 * A_BYTES;
        const uint32_t bl_b = bh_b + B_BYTES;

#pragma unroll
        for (int k16 = 0; k16 < 4; k16++) {
            const uint32_t kbyte = (uint32_t)(k16 * 32 + ahalf);
            uint32_t ahf[2][4], alf[2][4];
#pragma unroll
            for (int mf = 0; mf < 2; mf++) {
                uint32_t off = SWZ((uint32_t)((arow + mf * 16) * 128) + kbyte);
                ldsm4(ahf[mf], ah_b + off);
                ldsm4(alf[mf], al_b + off);
            }
#pragma unroll
            for (int g = 0; g < 3; g++) {
                uint32_t bhf[2][4], blf[2][4];
#pragma unroll
                for (int half = 0; half < 2; half++) {
                    uint32_t off = SWZ((uint32_t)((g * 64 + brow + half * 16) * 128) + kbyte);
                    ldsm4(bhf[half], bh_b + off);
                    ldsm4(blf[half], bl_b + off);
                }
#pragma unroll
                for (int mf = 0; mf < 2; mf++) {
#pragma unroll
                    for (int nf = 0; nf < 4; nf++) {
                        const int hv = nf >> 1, pr = nf & 1;
                        uint32_t bh0 = bhf[hv][pr], bh1 = bhf[hv][pr + 2];
                        uint32_t bl0 = blf[hv][pr], bl1 = blf[hv][pr + 2];
                        mma16816(acc[g][mf][nf], ahf[mf], bh0, bh1);
                        mma16816(acc[g][mf][nf], ahf[mf], bl0, bl1);
                        mma16816(acc[g][mf][nf], alf[mf], bh0, bh1);
                    }
                }
            }
        }
        __syncthreads();
    }

    // ---- fused gate epilogue ----
    const int ch_base = nt * CH + warp_c * 32 + (lane & 3) * 2;
    const int m_base  = m0 + warp_m * 32 + (lane >> 2);
#pragma unroll
    for (int mf = 0; mf < 2; mf++) {
#pragma unroll
        for (int nf = 0; nf < 4; nf++) {
#pragma unroll
            for (int r2 = 0; r2 < 2; r2++) {
                const int m = m_base + mf * 16 + r2 * 8;
                float2 va, vc;
                float* pa = &va.x; float* pc = &vc.x;
#pragma unroll
                for (int e = 0; e < 2; e++) {
                    float f  = acc[0][mf][nf][2 * r2 + e];
                    float iv = acc[1][mf][nf][2 * r2 + e];
                    float hv = acc[2][mf][nf][2 * r2 + e];
                    float diff = softplus_f(-f) - softplus_f(-iv);
                    float ex = expf(diff);
                    float fp = 1.0f / (1.0f + ex);      // sigmoid(-diff)
                    float ip = ex * fp;                  // sigmoid(diff)
                    float gv = (hv >= 0.0f) ? (hv + 0.5f)
                                            : 1.0f / (1.0f + expf(-hv));
                    pa[e] = fp;
                    pc[e] = ip * gv;
                }
                size_t o = (size_t)m * H_ + ch_base + nf * 8;
                *(float2*)&g_a[o] = va;
                *(float2*)&g_c[o] = vc;
            }
        }
    }
}

// ---------------------------------------------------------------------------
// Scan kernels (near DRAM roofline already)
// ---------------------------------------------------------------------------
__global__ __launch_bounds__(256) void k_chunk()
{
    const int bc = blockIdx.x;
    const int b  = bc / NCH;
    const int ch = bc % NCH;
    const int h  = threadIdx.x;
    size_t base = ((size_t)b * S_ + (size_t)ch * LCH) * H_ + h;

    float A = 1.0f, Bv = 0.0f;
#pragma unroll 8
    for (int t = 0; t < LCH; t++) {
        const float a = g_a[base + (size_t)t * H_];
        const float c = g_c[base + (size_t)t * H_];
        Bv = fmaf(a, Bv, c);
        A *= a;
    }
    g_Ae[(size_t)bc * H_ + h] = A;
    g_Be[(size_t)bc * H_ + h] = Bv;
}

__global__ void k_chain(const float* __restrict__ h_prev)
{
    const int idx = blockIdx.x * blockDim.x + threadIdx.x;
    const int b = idx / H_;
    const int h = idx % H_;

    const float z = h_prev[idx];
    float run = (z >= 0.0f) ? (z + 0.5f) : 1.0f / (1.0f + expf(-z));

    for (int k = 0; k < NCH; k++) {
        const size_t o = ((size_t)(b * NCH + k)) * H_ + h;
        g_h0[o] = run;
        run = fmaf(g_Ae[o], run, g_Be[o]);
    }
}

__global__ __launch_bounds__(256) void k_out(float* __restrict__ out)
{
    const int bc = blockIdx.x;
    const int b  = bc / NCH;
    const int ch = bc % NCH;
    const int h  = threadIdx.x;
    size_t base = ((size_t)b * S_ + (size_t)ch * LCH) * H_ + h;

    float hc = g_h0[(size_t)bc * H_ + h];
#pragma unroll 4
    for (int t = 0; t < LCH; t++) {
        const float a = g_a[base + (size_t)t * H_];
        const float c = g_c[base + (size_t)t * H_];
        hc = fmaf(a, hc, c);
        out[base + (size_t)t * H_] = hc;
    }
}

// ---------------------------------------------------------------------------
extern "C" void kernel_launch(void* const* d_in, const int* in_sizes, int n_in,
                              void* d_out, int out_size)
{
    const float* x  = nullptr;
    const float* hp = nullptr;
    const float* Wp = nullptr;
    for (int i = 0; i < n_in; i++) {
        if      (in_sizes[i] == M_ * D_)      x  = (const float*)d_in[i];
        else if (in_sizes[i] == B_ * H_)      hp = (const float*)d_in[i];
        else if (in_sizes[i] == 3 * H_ * D_)  Wp = (const float*)d_in[i];
    }
    float* out = (float*)d_out;

    cudaFuncSetAttribute(k_gemm_mma, cudaFuncAttributeMaxDynamicSharedMemorySize, SMEM_DYN);

    k_conv_x<<<(M_ * D_) / (256 * 4), 256>>>(x);
    k_conv_w<<<(N3H * D_) / (256 * 4), 256>>>(Wp);

    dim3 gg(NTILES, M_ / MT);          // (4, 512)
    k_gemm_mma<<<gg, 256, SMEM_DYN>>>();

    k_chunk<<<B_ * NCH, 256>>>();
    k_chain<<<(B_ * H_) / 256, 256>>>(hp);
    k_out<<<B_ * NCH, 256>>>(out);
}

// round 6
// speedup vs baseline: 2.9025x; 1.2935x over previous
#include <cuda_runtime.h>
#include <cuda_fp16.h>
#include <math.h>
#include <stdint.h>

// ---------------- problem constants ----------------
#define B_  8
#define S_  8192
#define D_  512
#define H_  256
#define M_  (B_*S_)            // 65536 rows
#define N3H (3*H_)             // 768

// ---------------- GEMM tiling (mma.sync path) ----------------
#define MT   128               // m rows per CTA (= one scan chunk)
#define CH   64                // channels per CTA
#define NT   192               // W rows per CTA = 3 gates x 64 ch
#define NTILES 4               // 256 / 64
#define KS   64                // k per SMEM stage (64 fp16 = 128 B rows, SW128)
#define NKS  (D_/KS)           // 8
#define A_BYTES (MT*128)       // 16384  (x, single fp16)
#define B_BYTES (NT*128)       // 24576  (each of wh / wl)
#define STAGE_BYTES (A_BYTES + 2*B_BYTES)     // 65536
#define SMEM_DYN (2*STAGE_BYTES)              // 131072

// scan chunking
#define LCH 128
#define NCH (S_/LCH)           // 64

// ---------------- device scratch ----------------
__device__ __half g_xh[(size_t)M_*D_];           // fp16(x)
__device__ __half g_wh[(size_t)N3H*D_];          // permuted [nt][192][512], hi
__device__ __half g_wl[(size_t)N3H*D_];          // lo
__device__ float g_a[(size_t)M_*H_];
__device__ float g_c[(size_t)M_*H_];
__device__ float g_Ae[(size_t)B_*NCH*H_];
__device__ float g_Be[(size_t)B_*NCH*H_];
__device__ float g_h0[(size_t)B_*NCH*H_];

// ---------------- PTX helpers ----------------
__device__ __forceinline__ uint32_t smem_u32(const void* p) {
    uint32_t a;
    asm("{ .reg .u64 t; cvta.to.shared.u64 t, %1; cvt.u32.u64 %0, t; }" : "=r"(a) : "l"(p));
    return a;
}
#define CP16(dst, src) asm volatile("cp.async.cg.shared.global [%0], [%1], 16;" :: "r"(dst), "l"(src) : "memory")
#define CP_COMMIT()    asm volatile("cp.async.commit_group;" ::: "memory")
#define CP_WAIT1()     asm volatile("cp.async.wait_group 1;" ::: "memory")
#define CP_WAIT0()     asm volatile("cp.async.wait_group 0;" ::: "memory")
#define SWZ(o) ((o) ^ (((o) >> 3) & 0x70))

__device__ __forceinline__ void ldsm4(uint32_t* r, uint32_t addr) {
    asm volatile("ldmatrix.sync.aligned.m8n8.x4.shared.b16 {%0,%1,%2,%3}, [%4];"
                 : "=r"(r[0]), "=r"(r[1]), "=r"(r[2]), "=r"(r[3]) : "r"(addr));
}
__device__ __forceinline__ void mma16816(float* d, const uint32_t* a,
                                         uint32_t b0, uint32_t b1) {
    asm volatile("mma.sync.aligned.m16n8k16.row.col.f32.f16.f16.f32 "
                 "{%0,%1,%2,%3}, {%4,%5,%6,%7}, {%8,%9}, {%0,%1,%2,%3};"
                 : "+f"(d[0]), "+f"(d[1]), "+f"(d[2]), "+f"(d[3])
                 : "r"(a[0]), "r"(a[1]), "r"(a[2]), "r"(a[3]), "r"(b0), "r"(b1));
}

__device__ __forceinline__ float softplus_f(float z) {
    return fmaxf(z, 0.0f) + log1pf(expf(-fabsf(z)));
}

// ---------------------------------------------------------------------------
// conversions
// ---------------------------------------------------------------------------
__global__ __launch_bounds__(256) void k_conv_x(const float* __restrict__ x)
{
    size_t i = ((size_t)blockIdx.x * blockDim.x + threadIdx.x) * 4;
    float4 v = *(const float4*)&x[i];
    __half2 p0 = __floats2half2_rn(v.x, v.y);
    __half2 p1 = __floats2half2_rn(v.z, v.w);
    *(__half2*)&g_xh[i]     = p0;
    *(__half2*)&g_xh[i + 2] = p1;
}

__global__ __launch_bounds__(256) void k_conv_w(const float* __restrict__ W)
{
    size_t i = ((size_t)blockIdx.x * blockDim.x + threadIdx.x) * 4;
    int r = (int)(i / D_);                 // src row 0..767
    int k = (int)(i % D_);
    int gate = r / H_, ch = r % H_;
    int ntv = ch / CH;
    size_t dst = ((size_t)(ntv * NT + gate * CH + (ch % CH))) * D_ + k;
    float4 v = *(const float4*)&W[i];
    __half hx = __float2half(v.x), hy = __float2half(v.y);
    __half hz = __float2half(v.z), hw = __float2half(v.w);
    g_wh[dst] = hx; g_wh[dst+1] = hy; g_wh[dst+2] = hz; g_wh[dst+3] = hw;
    g_wl[dst]   = __float2half(v.x - __half2float(hx));
    g_wl[dst+1] = __float2half(v.y - __half2float(hy));
    g_wl[dst+2] = __float2half(v.z - __half2float(hz));
    g_wl[dst+3] = __float2half(v.w - __half2float(hw));
}

// ---------------------------------------------------------------------------
// mma.sync fp16 GEMM + fused gate epilogue + fused per-chunk scan reduction.
// grid = (NTILES, M_/MT) = (4, 512); 256 threads (8 warps).
// ---------------------------------------------------------------------------
__global__ __launch_bounds__(256, 1) void k_gemm_mma()
{
    extern __shared__ char dynsmem[];
    const uint32_t sb = smem_u32(dynsmem);

    const int tid  = threadIdx.x;
    const int warp = tid >> 5;
    const int lane = tid & 31;
    const int warp_m = warp & 3;           // 0..3
    const int warp_c = warp >> 2;          // 0..1
    const int nt = blockIdx.x;
    const int m0 = blockIdx.y * MT;
    const int r0 = nt * NT;                // row base in permuted W

    // acc[gate][mfrag][nfrag][4]
    float acc[3][2][4][4];
#pragma unroll
    for (int g = 0; g < 3; g++)
#pragma unroll
        for (int mf = 0; mf < 2; mf++)
#pragma unroll
            for (int nf = 0; nf < 4; nf++)
#pragma unroll
                for (int e = 0; e < 4; e++) acc[g][mf][nf][e] = 0.0f;

    auto prefetch = [&](int ks) {
        const int st = ks & 1;
        const uint32_t ab = sb + st * STAGE_BYTES;
        const uint32_t bh = ab + A_BYTES;
        const uint32_t bl = bh + B_BYTES;
        const int kb = ks * KS;
#pragma unroll
        for (int it = 0; it < 4; it++) {   // A: 128 rows x 8 chunks = 1024
            int id = it * 256 + tid, row = id >> 3, cq = id & 7;
            uint32_t d = SWZ((uint32_t)(row * 128 + cq * 16));
            size_t so = (size_t)(m0 + row) * D_ + kb + cq * 8;
            CP16(ab + d, (const void*)(g_xh + so));
        }
#pragma unroll
        for (int it = 0; it < 6; it++) {   // B: 192 rows x 8 chunks = 1536
            int id = it * 256 + tid, row = id >> 3, cq = id & 7;
            uint32_t d = SWZ((uint32_t)(row * 128 + cq * 16));
            size_t so = (size_t)(r0 + row) * D_ + kb + cq * 8;
            CP16(bh + d, (const void*)(g_wh + so));
            CP16(bl + d, (const void*)(g_wl + so));
        }
        CP_COMMIT();
    };

    prefetch(0);

    const int arow = warp_m * 32 + (lane & 15);     // + mf*16
    const int ahalf = (lane >> 4) * 16;             // 16B k-half select
    const int brow = warp_c * 32 + (lane & 15);     // + gate*64 (+16 second half)

    for (int ks = 0; ks < NKS; ks++) {
        if (ks + 1 < NKS) { prefetch(ks + 1); CP_WAIT1(); }
        else             { CP_WAIT0(); }
        __syncthreads();

        const int st = ks & 1;
        const uint32_t ab_b = sb + st * STAGE_BYTES;
        const uint32_t bh_b = ab_b + A_BYTES;
        const uint32_t bl_b = bh_b + B_BYTES;

#pragma unroll
        for (int k16 = 0; k16 < 4; k16++) {
            const uint32_t kbyte = (uint32_t)(k16 * 32 + ahalf);
            uint32_t ahf[2][4];
#pragma unroll
            for (int mf = 0; mf < 2; mf++) {
                uint32_t off = SWZ((uint32_t)((arow + mf * 16) * 128) + kbyte);
                ldsm4(ahf[mf], ab_b + off);
            }
#pragma unroll
            for (int g = 0; g < 3; g++) {
                uint32_t bhf[2][4], blf[2][4];
#pragma unroll
                for (int half = 0; half < 2; half++) {
                    uint32_t off = SWZ((uint32_t)((g * 64 + brow + half * 16) * 128) + kbyte);
                    ldsm4(bhf[half], bh_b + off);
                    ldsm4(blf[half], bl_b + off);
                }
#pragma unroll
                for (int mf = 0; mf < 2; mf++) {
#pragma unroll
                    for (int nf = 0; nf < 4; nf++) {
                        const int hv = nf >> 1, pr = nf & 1;
                        mma16816(acc[g][mf][nf], ahf[mf], bhf[hv][pr], bhf[hv][pr + 2]);
                        mma16816(acc[g][mf][nf], ahf[mf], blf[hv][pr], blf[hv][pr + 2]);
                    }
                }
            }
        }
        __syncthreads();
    }

    // ---- fused gate epilogue: write a,c to gmem + stage into smem ----
    float* sA = (float*)dynsmem;                 // [128][65] padded
    float* sC = sA + 128 * 65;                   // [128][65]

    const int chl_base = warp_c * 32 + (lane & 3) * 2;
    const int ch_gbase = nt * CH + chl_base;
    const int m_base   = m0 + warp_m * 32 + (lane >> 2);
#pragma unroll
    for (int mf = 0; mf < 2; mf++) {
#pragma unroll
        for (int nf = 0; nf < 4; nf++) {
#pragma unroll
            for (int r2 = 0; r2 < 2; r2++) {
                const int m = m_base + mf * 16 + r2 * 8;
                const int t = m - m0;
                float2 va, vc;
                float* pa = &va.x; float* pc = &vc.x;
#pragma unroll
                for (int e = 0; e < 2; e++) {
                    float f  = acc[0][mf][nf][2 * r2 + e];
                    float iv = acc[1][mf][nf][2 * r2 + e];
                    float hv = acc[2][mf][nf][2 * r2 + e];
                    float diff = softplus_f(-f) - softplus_f(-iv);
                    float ex = expf(diff);
                    float fp = 1.0f / (1.0f + ex);      // sigmoid(-diff)
                    float ip = ex * fp;                  // sigmoid(diff)
                    float gv = (hv >= 0.0f) ? (hv + 0.5f)
                                            : 1.0f / (1.0f + expf(-hv));
                    pa[e] = fp;
                    pc[e] = ip * gv;
                    const int chl = chl_base + nf * 8 + e;
                    sA[t * 65 + chl] = fp;
                    sC[t * 65 + chl] = ip * gv;
                }
                size_t o = (size_t)m * H_ + ch_gbase + nf * 8;
                *(float2*)&g_a[o] = va;
                *(float2*)&g_c[o] = vc;
            }
        }
    }
    __syncthreads();

    // ---- fused chunk reduction: 64 threads, one per channel ----
    if (tid < 64) {
        float A = 1.0f, Bv = 0.0f;
#pragma unroll 8
        for (int t = 0; t < LCH; t++) {
            const float a = sA[t * 65 + tid];
            const float c = sC[t * 65 + tid];
            Bv = fmaf(a, Bv, c);
            A *= a;
        }
        const int b   = m0 >> 13;          // m0 / 8192
        const int chk = (m0 & 8191) >> 7;  // chunk within batch
        const size_t o = (size_t)(b * NCH + chk) * H_ + nt * CH + tid;
        g_Ae[o] = A;
        g_Be[o] = Bv;
    }
}

// ---------------------------------------------------------------------------
// cross-chunk chain + output replay
// ---------------------------------------------------------------------------
__global__ void k_chain(const float* __restrict__ h_prev)
{
    const int idx = blockIdx.x * blockDim.x + threadIdx.x;
    const int b = idx / H_;
    const int h = idx % H_;

    const float z = h_prev[idx];
    float run = (z >= 0.0f) ? (z + 0.5f) : 1.0f / (1.0f + expf(-z));

    for (int k = 0; k < NCH; k++) {
        const size_t o = ((size_t)(b * NCH + k)) * H_ + h;
        g_h0[o] = run;
        run = fmaf(g_Ae[o], run, g_Be[o]);
    }
}

__global__ __launch_bounds__(256) void k_out(float* __restrict__ out)
{
    const int bc = blockIdx.x;
    const int b  = bc / NCH;
    const int ch = bc % NCH;
    const int h  = threadIdx.x;
    size_t base = ((size_t)b * S_ + (size_t)ch * LCH) * H_ + h;

    float hc = g_h0[(size_t)bc * H_ + h];
#pragma unroll 4
    for (int t = 0; t < LCH; t++) {
        const float a = g_a[base + (size_t)t * H_];
        const float c = g_c[base + (size_t)t * H_];
        hc = fmaf(a, hc, c);
        out[base + (size_t)t * H_] = hc;
    }
}

// ---------------------------------------------------------------------------
extern "C" void kernel_launch(void* const* d_in, const int* in_sizes, int n_in,
                              void* d_out, int out_size)
{
    const float* x  = nullptr;
    const float* hp = nullptr;
    const float* Wp = nullptr;
    for (int i = 0; i < n_in; i++) {
        if      (in_sizes[i] == M_ * D_)      x  = (const float*)d_in[i];
        else if (in_sizes[i] == B_ * H_)      hp = (const float*)d_in[i];
        else if (in_sizes[i] == 3 * H_ * D_)  Wp = (const float*)d_in[i];
    }
    float* out = (float*)d_out;

    cudaFuncSetAttribute(k_gemm_mma, cudaFuncAttributeMaxDynamicSharedMemorySize, SMEM_DYN);

    k_conv_x<<<(M_ * D_) / (256 * 4), 256>>>(x);
    k_conv_w<<<(N3H * D_) / (256 * 4), 256>>>(Wp);

    dim3 gg(NTILES, M_ / MT);          // (4, 512)
    k_gemm_mma<<<gg, 256, SMEM_DYN>>>();

    k_chain<<<(B_ * H_) / 256, 256>>>(hp);
    k_out<<<B_ * NCH, 256>>>(out);
}

// round 9
// speedup vs baseline: 3.9919x; 1.3753x over previous
#include <cuda_runtime.h>
#include <cuda_fp16.h>
#include <math.h>
#include <stdint.h>

// ---------------- problem constants ----------------
#define B_  8
#define S_  8192
#define D_  512
#define H_  256
#define M_  (B_*S_)            // 65536 rows
#define N3H (3*H_)             // 768

// ---------------- GEMM tiling (mma.sync path) ----------------
#define MT   128               // m rows per CTA (= one scan chunk)
#define CH   64                // channels per CTA
#define NT   192               // W rows per CTA = 3 gates x 64 ch
#define NTILES 4               // 256 / 64
#define KS   64                // k per SMEM stage (64 fp16 = 128 B rows, SW128)
#define NKS  (D_/KS)           // 8
#define A_BYTES (MT*128)       // 16384  (x fp16)
#define B_BYTES (NT*128)       // 24576  (W fp16)
#define STAGE_BYTES (A_BYTES + B_BYTES)       // 40960
#define SMEM_DYN (2*STAGE_BYTES)              // 81920

// scan chunking
#define LCH 128
#define NCH (S_/LCH)           // 64

// ---------------- device scratch ----------------
__device__ __half g_xh[(size_t)M_*D_];           // fp16(x)
__device__ __half g_wh[(size_t)N3H*D_];          // permuted [nt][192][512]
__device__ float g_a[(size_t)M_*H_];
__device__ float g_c[(size_t)M_*H_];
__device__ float g_Ae[(size_t)B_*NCH*H_];
__device__ float g_Be[(size_t)B_*NCH*H_];
__device__ float g_h0[(size_t)B_*NCH*H_];

// ---------------- PTX helpers ----------------
__device__ __forceinline__ uint32_t smem_u32(const void* p) {
    uint32_t a;
    asm("{ .reg .u64 t; cvta.to.shared.u64 t, %1; cvt.u32.u64 %0, t; }" : "=r"(a) : "l"(p));
    return a;
}
#define CP16(dst, src) asm volatile("cp.async.cg.shared.global [%0], [%1], 16;" :: "r"(dst), "l"(src) : "memory")
#define CP_COMMIT()    asm volatile("cp.async.commit_group;" ::: "memory")
#define CP_WAIT1()     asm volatile("cp.async.wait_group 1;" ::: "memory")
#define CP_WAIT0()     asm volatile("cp.async.wait_group 0;" ::: "memory")
#define SWZ(o) ((o) ^ (((o) >> 3) & 0x70))

__device__ __forceinline__ void ldsm4(uint32_t* r, uint32_t addr) {
    asm volatile("ldmatrix.sync.aligned.m8n8.x4.shared.b16 {%0,%1,%2,%3}, [%4];"
                 : "=r"(r[0]), "=r"(r[1]), "=r"(r[2]), "=r"(r[3]) : "r"(addr));
}
__device__ __forceinline__ void mma16816(float* d, const uint32_t* a,
                                         uint32_t b0, uint32_t b1) {
    asm volatile("mma.sync.aligned.m16n8k16.row.col.f32.f16.f16.f32 "
                 "{%0,%1,%2,%3}, {%4,%5,%6,%7}, {%8,%9}, {%0,%1,%2,%3};"
                 : "+f"(d[0]), "+f"(d[1]), "+f"(d[2]), "+f"(d[3])
                 : "r"(a[0]), "r"(a[1]), "r"(a[2]), "r"(a[3]), "r"(b0), "r"(b1));
}

__device__ __forceinline__ float softplus_f(float z) {
    return fmaxf(z, 0.0f) + log1pf(expf(-fabsf(z)));
}

// ---------------------------------------------------------------------------
// conversions
// ---------------------------------------------------------------------------
__global__ __launch_bounds__(256) void k_conv_x(const float* __restrict__ x)
{
    size_t i = ((size_t)blockIdx.x * blockDim.x + threadIdx.x) * 4;
    float4 v = *(const float4*)&x[i];
    *(__half2*)&g_xh[i]     = __floats2half2_rn(v.x, v.y);
    *(__half2*)&g_xh[i + 2] = __floats2half2_rn(v.z, v.w);
}

__global__ __launch_bounds__(256) void k_conv_w(const float* __restrict__ W)
{
    size_t i = ((size_t)blockIdx.x * blockDim.x + threadIdx.x) * 4;
    int r = (int)(i / D_);                 // src row 0..767
    int k = (int)(i % D_);
    int gate = r / H_, ch = r % H_;
    int ntv = ch / CH;
    size_t dst = ((size_t)(ntv * NT + gate * CH + (ch % CH))) * D_ + k;
    float4 v = *(const float4*)&W[i];
    g_wh[dst]   = __float2half(v.x);
    g_wh[dst+1] = __float2half(v.y);
    g_wh[dst+2] = __float2half(v.z);
    g_wh[dst+3] = __float2half(v.w);
}

// ---------------------------------------------------------------------------
// mma.sync fp16 GEMM + fused gate epilogue + fused per-chunk scan reduction.
// grid = (NTILES, M_/MT) = (4, 512); 256 threads (8 warps).
// ---------------------------------------------------------------------------
__global__ __launch_bounds__(256, 1) void k_gemm_mma()
{
    extern __shared__ char dynsmem[];
    const uint32_t sb = smem_u32(dynsmem);

    const int tid  = threadIdx.x;
    const int warp = tid >> 5;
    const int lane = tid & 31;
    const int warp_m = warp & 3;           // 0..3
    const int warp_c = warp >> 2;          // 0..1
    const int nt = blockIdx.x;
    const int m0 = blockIdx.y * MT;
    const int r0 = nt * NT;                // row base in permuted W

    float acc[3][2][4][4];
#pragma unroll
    for (int g = 0; g < 3; g++)
#pragma unroll
        for (int mf = 0; mf < 2; mf++)
#pragma unroll
            for (int nf = 0; nf < 4; nf++)
#pragma unroll
                for (int e = 0; e < 4; e++) acc[g][mf][nf][e] = 0.0f;

    auto prefetch = [&](int ks) {
        const int st = ks & 1;
        const uint32_t ab = sb + st * STAGE_BYTES;
        const uint32_t bh = ab + A_BYTES;
        const int kb = ks * KS;
#pragma unroll
        for (int it = 0; it < 4; it++) {   // A: 128 rows x 8 chunks = 1024
            int id = it * 256 + tid, row = id >> 3, cq = id & 7;
            uint32_t d = SWZ((uint32_t)(row * 128 + cq * 16));
            size_t so = (size_t)(m0 + row) * D_ + kb + cq * 8;
            CP16(ab + d, (const void*)(g_xh + so));
        }
#pragma unroll
        for (int it = 0; it < 6; it++) {   // B: 192 rows x 8 chunks = 1536
            int id = it * 256 + tid, row = id >> 3, cq = id & 7;
            uint32_t d = SWZ((uint32_t)(row * 128 + cq * 16));
            size_t so = (size_t)(r0 + row) * D_ + kb + cq * 8;
            CP16(bh + d, (const void*)(g_wh + so));
        }
        CP_COMMIT();
    };

    prefetch(0);

    const int arow = warp_m * 32 + (lane & 15);     // + mf*16
    const int ahalf = (lane >> 4) * 16;             // 16B k-half select
    const int brow = warp_c * 32 + (lane & 15);     // + gate*64 (+16 second half)

    for (int ks = 0; ks < NKS; ks++) {
        if (ks + 1 < NKS) { prefetch(ks + 1); CP_WAIT1(); }
        else             { CP_WAIT0(); }
        __syncthreads();

        const int st = ks & 1;
        const uint32_t ab_b = sb + st * STAGE_BYTES;
        const uint32_t bh_b = ab_b + A_BYTES;

#pragma unroll
        for (int k16 = 0; k16 < 4; k16++) {
            const uint32_t kbyte = (uint32_t)(k16 * 32 + ahalf);
            uint32_t ahf[2][4];
#pragma unroll
            for (int mf = 0; mf < 2; mf++) {
                uint32_t off = SWZ((uint32_t)((arow + mf * 16) * 128) + kbyte);
                ldsm4(ahf[mf], ab_b + off);
            }
#pragma unroll
            for (int g = 0; g < 3; g++) {
                uint32_t bhf[2][4];
#pragma unroll
                for (int half = 0; half < 2; half++) {
                    uint32_t off = SWZ((uint32_t)((g * 64 + brow + half * 16) * 128) + kbyte);
                    ldsm4(bhf[half], bh_b + off);
                }
#pragma unroll
                for (int mf = 0; mf < 2; mf++) {
#pragma unroll
                    for (int nf = 0; nf < 4; nf++) {
                        const int hv = nf >> 1, pr = nf & 1;
                        mma16816(acc[g][mf][nf], ahf[mf], bhf[hv][pr], bhf[hv][pr + 2]);
                    }
                }
            }
        }
        __syncthreads();
    }

    // ---- fused gate epilogue: write a,c to gmem + stage into smem ----
    float* sA = (float*)dynsmem;                 // [128][65] padded
    float* sC = sA + 128 * 65;

    const int chl_base = warp_c * 32 + (lane & 3) * 2;
    const int ch_gbase = nt * CH + chl_base;
    const int m_base   = m0 + warp_m * 32 + (lane >> 2);
#pragma unroll
    for (int mf = 0; mf < 2; mf++) {
#pragma unroll
        for (int nf = 0; nf < 4; nf++) {
#pragma unroll
            for (int r2 = 0; r2 < 2; r2++) {
                const int m = m_base + mf * 16 + r2 * 8;
                const int t = m - m0;
                float2 va, vc;
                float* pa = &va.x; float* pc = &vc.x;
#pragma unroll
                for (int e = 0; e < 2; e++) {
                    float f  = acc[0][mf][nf][2 * r2 + e];
                    float iv = acc[1][mf][nf][2 * r2 + e];
                    float hv = acc[2][mf][nf][2 * r2 + e];
                    float diff = softplus_f(-f) - softplus_f(-iv);
                    float ex = expf(diff);
                    float fp = 1.0f / (1.0f + ex);      // sigmoid(-diff)
                    float ip = ex * fp;                  // sigmoid(diff)
                    float gv = (hv >= 0.0f) ? (hv + 0.5f)
                                            : 1.0f / (1.0f + expf(-hv));
                    pa[e] = fp;
                    pc[e] = ip * gv;
                    const int chl = chl_base + nf * 8 + e;
                    sA[t * 65 + chl] = fp;
                    sC[t * 65 + chl] = ip * gv;
                }
                size_t o = (size_t)m * H_ + ch_gbase + nf * 8;
                *(float2*)&g_a[o] = va;
                *(float2*)&g_c[o] = vc;
            }
        }
    }
    __syncthreads();

    // ---- fused chunk reduction: 64 threads, one per channel ----
    if (tid < 64) {
        float A = 1.0f, Bv = 0.0f;
#pragma unroll 8
        for (int t = 0; t < LCH; t++) {
            const float a = sA[t * 65 + tid];
            const float c = sC[t * 65 + tid];
            Bv = fmaf(a, Bv, c);
            A *= a;
        }
        const int b   = m0 >> 13;
        const int chk = (m0 & 8191) >> 7;
        const size_t o = (size_t)(b * NCH + chk) * H_ + nt * CH + tid;
        g_Ae[o] = A;
        g_Be[o] = Bv;
    }
}

// ---------------------------------------------------------------------------
// cross-chunk chain: one warp per (b,h) channel; lane owns chunks 2l, 2l+1.
// Affine compose (earlier L, later R): (A,B) = (A_L*A_R, A_R*B_L + B_R).
// ---------------------------------------------------------------------------
__global__ __launch_bounds__(256) void k_chain(const float* __restrict__ h_prev)
{
    const int gw   = (blockIdx.x * blockDim.x + threadIdx.x) >> 5;  // channel id
    const int lane = threadIdx.x & 31;
    const int b = gw / H_;
    const int h = gw % H_;

    const size_t o0 = ((size_t)(b * NCH + 2 * lane)) * H_ + h;
    const float A0 = g_Ae[o0],       B0 = g_Be[o0];
    const float A1 = g_Ae[o0 + H_],  B1 = g_Be[o0 + H_];

    // lane-local pair (chunk 2l then 2l+1)
    float As = A0 * A1;
    float Bs = fmaf(A1, B0, B1);

    // warp-inclusive scan
#pragma unroll
    for (int d = 1; d < 32; d <<= 1) {
        float Au = __shfl_up_sync(0xFFFFFFFFu, As, d);
        float Bu = __shfl_up_sync(0xFFFFFFFFu, Bs, d);
        if (lane >= d) {
            Bs = fmaf(As, Bu, Bs);
            As = As * Au;
        }
    }
    // exclusive prefix
    float Ae = __shfl_up_sync(0xFFFFFFFFu, As, 1);
    float Be = __shfl_up_sync(0xFFFFFFFFu, Bs, 1);
    if (lane == 0) { Ae = 1.0f; Be = 0.0f; }

    const float z = h_prev[b * H_ + h];
    const float init = (z >= 0.0f) ? (z + 0.5f) : 1.0f / (1.0f + expf(-z));

    const float h0a = fmaf(Ae, init, Be);       // start of chunk 2l
    const float h0b = fmaf(A0, h0a, B0);        // start of chunk 2l+1
    g_h0[o0]      = h0a;
    g_h0[o0 + H_] = h0b;
}

// ---------------------------------------------------------------------------
__global__ __launch_bounds__(256) void k_out(float* __restrict__ out)
{
    const int bc = blockIdx.x;
    const int b  = bc / NCH;
    const int ch = bc % NCH;
    const int h  = threadIdx.x;
    size_t base = ((size_t)b * S_ + (size_t)ch * LCH) * H_ + h;

    float hc = g_h0[(size_t)bc * H_ + h];
#pragma unroll 4
    for (int t = 0; t < LCH; t++) {
        const float a = g_a[base + (size_t)t * H_];
        const float c = g_c[base + (size_t)t * H_];
        hc = fmaf(a, hc, c);
        out[base + (size_t)t * H_] = hc;
    }
}

// ---------------------------------------------------------------------------
extern "C" void kernel_launch(void* const* d_in, const int* in_sizes, int n_in,
                              void* d_out, int out_size)
{
    const float* x  = nullptr;
    const float* hp = nullptr;
    const float* Wp = nullptr;
    for (int i = 0; i < n_in; i++) {
        if      (in_sizes[i] == M_ * D_)      x  = (const float*)d_in[i];
        else if (in_sizes[i] == B_ * H_)      hp = (const float*)d_in[i];
        else if (in_sizes[i] == 3 * H_ * D_)  Wp = (const float*)d_in[i];
    }
    float* out = (float*)d_out;

    cudaFuncSetAttribute(k_gemm_mma, cudaFuncAttributeMaxDynamicSharedMemorySize, SMEM_DYN);

    k_conv_x<<<(M_ * D_) / (256 * 4), 256>>>(x);
    k_conv_w<<<(N3H * D_) / (256 * 4), 256>>>(Wp);

    dim3 gg(NTILES, M_ / MT);          // (4, 512)
    k_gemm_mma<<<gg, 256, SMEM_DYN>>>();

    k_chain<<<(B_ * H_ * 32) / 256, 256>>>(hp);
    k_out<<<B_ * NCH, 256>>>(out);
}

// round 10
// speedup vs baseline: 4.7867x; 1.1991x over previous
#include <cuda_runtime.h>
#include <cuda_fp16.h>
#include <math.h>
#include <stdint.h>

// ---------------- problem constants ----------------
#define B_  8
#define S_  8192
#define D_  512
#define H_  256
#define M_  (B_*S_)            // 65536 rows
#define N3H (3*H_)             // 768

// ---------------- GEMM tiling (mma.sync path) ----------------
#define MT   128               // m rows per CTA (= one scan chunk)
#define CH   64                // channels per CTA
#define NT   192               // W rows per CTA = 3 gates x 64 ch
#define NTILES 4               // 256 / 64
#define KS   64                // k per SMEM stage (64 fp16 = 128 B rows, SW128)
#define NKS  (D_/KS)           // 8
#define A_BYTES (MT*128)       // 16384  (x fp16)
#define B_BYTES (NT*128)       // 24576  (W fp16)
#define STAGE_BYTES (A_BYTES + B_BYTES)       // 40960
#define SMEM_DYN (2*STAGE_BYTES)              // 81920

// scan chunking
#define LCH 128
#define NCH (S_/LCH)           // 64

// ---------------- device scratch ----------------
__device__ __half g_wh[(size_t)N3H*D_];          // permuted [nt][192][512]
__device__ __half g_a[(size_t)M_*H_];            // forget gate (fp16)
__device__ __half g_c[(size_t)M_*H_];            // input contribution (fp16)
__device__ float g_Ae[(size_t)B_*NCH*H_];
__device__ float g_Be[(size_t)B_*NCH*H_];
__device__ float g_h0[(size_t)B_*NCH*H_];

// ---------------- PTX helpers ----------------
__device__ __forceinline__ uint32_t smem_u32(const void* p) {
    uint32_t a;
    asm("{ .reg .u64 t; cvta.to.shared.u64 t, %1; cvt.u32.u64 %0, t; }" : "=r"(a) : "l"(p));
    return a;
}
#define CP16(dst, src) asm volatile("cp.async.cg.shared.global [%0], [%1], 16;" :: "r"(dst), "l"(src) : "memory")
#define CP_COMMIT()    asm volatile("cp.async.commit_group;" ::: "memory")
#define CP_WAIT1()     asm volatile("cp.async.wait_group 1;" ::: "memory")
#define CP_WAIT0()     asm volatile("cp.async.wait_group 0;" ::: "memory")
#define SWZ(o) ((o) ^ (((o) >> 3) & 0x70))

__device__ __forceinline__ void ldsm4(uint32_t* r, uint32_t addr) {
    asm volatile("ldmatrix.sync.aligned.m8n8.x4.shared.b16 {%0,%1,%2,%3}, [%4];"
                 : "=r"(r[0]), "=r"(r[1]), "=r"(r[2]), "=r"(r[3]) : "r"(addr));
}
__device__ __forceinline__ void mma16816(float* d, const uint32_t* a,
                                         uint32_t b0, uint32_t b1) {
    asm volatile("mma.sync.aligned.m16n8k16.row.col.f32.f16.f16.f32 "
                 "{%0,%1,%2,%3}, {%4,%5,%6,%7}, {%8,%9}, {%0,%1,%2,%3};"
                 : "+f"(d[0]), "+f"(d[1]), "+f"(d[2]), "+f"(d[3])
                 : "r"(a[0]), "r"(a[1]), "r"(a[2]), "r"(a[3]), "r"(b0), "r"(b1));
}

__device__ __forceinline__ float softplus_f(float z) {
    return fmaxf(z, 0.0f) + __logf(1.0f + __expf(-fabsf(z)));
}

// ---------------------------------------------------------------------------
// W conversion/permute (tiny: 1.5 MB)
// ---------------------------------------------------------------------------
__global__ __launch_bounds__(256) void k_conv_w(const float* __restrict__ W)
{
    size_t i = ((size_t)blockIdx.x * blockDim.x + threadIdx.x) * 4;
    int r = (int)(i / D_);                 // src row 0..767
    int k = (int)(i % D_);
    int gate = r / H_, ch = r % H_;
    int ntv = ch / CH;
    size_t dst = ((size_t)(ntv * NT + gate * CH + (ch % CH))) * D_ + k;
    float4 v = *(const float4*)&W[i];
    g_wh[dst]   = __float2half(v.x);
    g_wh[dst+1] = __float2half(v.y);
    g_wh[dst+2] = __float2half(v.z);
    g_wh[dst+3] = __float2half(v.w);
}

// ---------------------------------------------------------------------------
// mma.sync fp16 GEMM + fused gate epilogue + fused per-chunk scan reduction.
// x loaded fp32 from gmem, converted in-kernel (LDG->reg->STS fp16).
// grid = (NTILES, M_/MT) = (4, 512); 256 threads (8 warps).
// ---------------------------------------------------------------------------
__global__ __launch_bounds__(256, 1) void k_gemm_mma(const float* __restrict__ x)
{
    extern __shared__ char dynsmem[];
    const uint32_t sb = smem_u32(dynsmem);

    const int tid  = threadIdx.x;
    const int warp = tid >> 5;
    const int lane = tid & 31;
    const int warp_m = warp & 3;           // 0..3
    const int warp_c = warp >> 2;          // 0..1
    const int nt = blockIdx.x;
    const int m0 = blockIdx.y * MT;
    const int r0 = nt * NT;                // row base in permuted W

    float acc[3][2][4][4];
#pragma unroll
    for (int g = 0; g < 3; g++)
#pragma unroll
        for (int mf = 0; mf < 2; mf++)
#pragma unroll
            for (int nf = 0; nf < 4; nf++)
#pragma unroll
                for (int e = 0; e < 4; e++) acc[g][mf][nf][e] = 0.0f;

    // A tile: 128 rows x 64 k fp32 -> fp16. Per thread: 4 chunks of 8 floats.
    float4 av[8];
    auto lda = [&](int ks) {
        const int kb = ks * KS;
#pragma unroll
        for (int it = 0; it < 4; it++) {
            int id = it * 256 + tid, row = id >> 3, cq = id & 7;
            size_t so = (size_t)(m0 + row) * D_ + kb + cq * 8;
            av[2 * it]     = *(const float4*)&x[so];
            av[2 * it + 1] = *(const float4*)&x[so + 4];
        }
    };
    auto sta = [&](int ks) {
        const int st = ks & 1;
#pragma unroll
        for (int it = 0; it < 4; it++) {
            int id = it * 256 + tid, row = id >> 3, cq = id & 7;
            uint32_t d = SWZ((uint32_t)(row * 128 + cq * 16));
            __half2 h0 = __floats2half2_rn(av[2 * it].x,     av[2 * it].y);
            __half2 h1 = __floats2half2_rn(av[2 * it].z,     av[2 * it].w);
            __half2 h2 = __floats2half2_rn(av[2 * it + 1].x, av[2 * it + 1].y);
            __half2 h3 = __floats2half2_rn(av[2 * it + 1].z, av[2 * it + 1].w);
            uint4 u;
            u.x = *(uint32_t*)&h0; u.y = *(uint32_t*)&h1;
            u.z = *(uint32_t*)&h2; u.w = *(uint32_t*)&h3;
            *(uint4*)(dynsmem + st * STAGE_BYTES + d) = u;
        }
    };
    auto prefetch_w = [&](int ks) {
        const int st = ks & 1;
        const uint32_t bh = sb + st * STAGE_BYTES + A_BYTES;
        const int kb = ks * KS;
#pragma unroll
        for (int it = 0; it < 6; it++) {   // B: 192 rows x 8 chunks = 1536
            int id = it * 256 + tid, row = id >> 3, cq = id & 7;
            uint32_t d = SWZ((uint32_t)(row * 128 + cq * 16));
            size_t so = (size_t)(r0 + row) * D_ + kb + cq * 8;
            CP16(bh + d, (const void*)(g_wh + so));
        }
        CP_COMMIT();
    };

    lda(0); sta(0);
    prefetch_w(0);

    const int arow = warp_m * 32 + (lane & 15);     // + mf*16
    const int ahalf = (lane >> 4) * 16;             // 16B k-half select
    const int brow = warp_c * 32 + (lane & 15);     // + gate*64 (+16 second half)

    for (int ks = 0; ks < NKS; ks++) {
        if (ks + 1 < NKS) { lda(ks + 1); prefetch_w(ks + 1); CP_WAIT1(); }
        else             { CP_WAIT0(); }
        __syncthreads();

        const int st = ks & 1;
        const uint32_t ab_b = sb + st * STAGE_BYTES;
        const uint32_t bh_b = ab_b + A_BYTES;

#pragma unroll
        for (int k16 = 0; k16 < 4; k16++) {
            const uint32_t kbyte = (uint32_t)(k16 * 32 + ahalf);
            uint32_t ahf[2][4];
#pragma unroll
            for (int mf = 0; mf < 2; mf++) {
                uint32_t off = SWZ((uint32_t)((arow + mf * 16) * 128) + kbyte);
                ldsm4(ahf[mf], ab_b + off);
            }
#pragma unroll
            for (int g = 0; g < 3; g++) {
                uint32_t bhf[2][4];
#pragma unroll
                for (int half = 0; half < 2; half++) {
                    uint32_t off = SWZ((uint32_t)((g * 64 + brow + half * 16) * 128) + kbyte);
                    ldsm4(bhf[half], bh_b + off);
                }
#pragma unroll
                for (int mf = 0; mf < 2; mf++) {
#pragma unroll
                    for (int nf = 0; nf < 4; nf++) {
                        const int hv = nf >> 1, pr = nf & 1;
                        mma16816(acc[g][mf][nf], ahf[mf], bhf[hv][pr], bhf[hv][pr + 2]);
                    }
                }
            }
        }
        if (ks + 1 < NKS) sta(ks + 1);      // next iter's __syncthreads publishes
    }
    __syncthreads();                         // smem reuse for sA/sC below

    // ---- fused gate epilogue: write a,c to gmem (fp16) + stage into smem ----
    float* sA = (float*)dynsmem;                 // [128][65] padded
    float* sC = sA + 128 * 65;

    const int chl_base = warp_c * 32 + (lane & 3) * 2;
    const int ch_gbase = nt * CH + chl_base;
    const int m_base   = m0 + warp_m * 32 + (lane >> 2);
#pragma unroll
    for (int mf = 0; mf < 2; mf++) {
#pragma unroll
        for (int nf = 0; nf < 4; nf++) {
#pragma unroll
            for (int r2 = 0; r2 < 2; r2++) {
                const int m = m_base + mf * 16 + r2 * 8;
                const int t = m - m0;
                float fpv[2], cv[2];
#pragma unroll
                for (int e = 0; e < 2; e++) {
                    float f  = acc[0][mf][nf][2 * r2 + e];
                    float iv = acc[1][mf][nf][2 * r2 + e];
                    float hv = acc[2][mf][nf][2 * r2 + e];
                    float diff = softplus_f(-f) - softplus_f(-iv);
                    float ex = __expf(diff);
                    float fp = 1.0f / (1.0f + ex);      // sigmoid(-diff)
                    float ip = ex * fp;                  // sigmoid(diff)
                    float gv = (hv >= 0.0f) ? (hv + 0.5f)
                                            : 1.0f / (1.0f + __expf(-hv));
                    fpv[e] = fp;
                    cv[e]  = ip * gv;
                    const int chl = chl_base + nf * 8 + e;
                    sA[t * 65 + chl] = fp;
                    sC[t * 65 + chl] = cv[e];
                }
                size_t o = (size_t)m * H_ + ch_gbase + nf * 8;
                *(__half2*)&g_a[o] = __floats2half2_rn(fpv[0], fpv[1]);
                *(__half2*)&g_c[o] = __floats2half2_rn(cv[0],  cv[1]);
            }
        }
    }
    __syncthreads();

    // ---- fused chunk reduction: 64 threads, one per channel ----
    if (tid < 64) {
        float A = 1.0f, Bv = 0.0f;
#pragma unroll 8
        for (int t = 0; t < LCH; t++) {
            const float a = sA[t * 65 + tid];
            const float c = sC[t * 65 + tid];
            Bv = fmaf(a, Bv, c);
            A *= a;
        }
        const int b   = m0 >> 13;
        const int chk = (m0 & 8191) >> 7;
        const size_t o = (size_t)(b * NCH + chk) * H_ + nt * CH + tid;
        g_Ae[o] = A;
        g_Be[o] = Bv;
    }
}

// ---------------------------------------------------------------------------
// cross-chunk chain: one warp per (b,h) channel; lane owns chunks 2l, 2l+1.
// ---------------------------------------------------------------------------
__global__ __launch_bounds__(256) void k_chain(const float* __restrict__ h_prev)
{
    const int gw   = (blockIdx.x * blockDim.x + threadIdx.x) >> 5;  // channel id
    const int lane = threadIdx.x & 31;
    const int b = gw / H_;
    const int h = gw % H_;

    const size_t o0 = ((size_t)(b * NCH + 2 * lane)) * H_ + h;
    const float A0 = g_Ae[o0],       B0 = g_Be[o0];
    const float A1 = g_Ae[o0 + H_],  B1 = g_Be[o0 + H_];

    float As = A0 * A1;
    float Bs = fmaf(A1, B0, B1);

#pragma unroll
    for (int d = 1; d < 32; d <<= 1) {
        float Au = __shfl_up_sync(0xFFFFFFFFu, As, d);
        float Bu = __shfl_up_sync(0xFFFFFFFFu, Bs, d);
        if (lane >= d) {
            Bs = fmaf(As, Bu, Bs);
            As = As * Au;
        }
    }
    float Ae = __shfl_up_sync(0xFFFFFFFFu, As, 1);
    float Be = __shfl_up_sync(0xFFFFFFFFu, Bs, 1);
    if (lane == 0) { Ae = 1.0f; Be = 0.0f; }

    const float z = h_prev[b * H_ + h];
    const float init = (z >= 0.0f) ? (z + 0.5f) : 1.0f / (1.0f + __expf(-z));

    const float h0a = fmaf(Ae, init, Be);
    const float h0b = fmaf(A0, h0a, B0);
    g_h0[o0]      = h0a;
    g_h0[o0 + H_] = h0b;
}

// ---------------------------------------------------------------------------
// output replay: 128 threads per (b,chunk), each thread owns 2 channels.
// ---------------------------------------------------------------------------
__global__ __launch_bounds__(128) void k_out(float* __restrict__ out)
{
    const int bc = blockIdx.x;
    const int b  = bc / NCH;
    const int ch = bc % NCH;
    const int h2 = threadIdx.x * 2;
    size_t base = ((size_t)b * S_ + (size_t)ch * LCH) * H_ + h2;

    float hc0 = g_h0[(size_t)bc * H_ + h2];
    float hc1 = g_h0[(size_t)bc * H_ + h2 + 1];
#pragma unroll 4
    for (int t = 0; t < LCH; t++) {
        const size_t o = base + (size_t)t * H_;
        const __half2 a2 = *(const __half2*)&g_a[o];
        const __half2 c2 = *(const __half2*)&g_c[o];
        const float2 af = __half22float2(a2);
        const float2 cf = __half22float2(c2);
        hc0 = fmaf(af.x, hc0, cf.x);
        hc1 = fmaf(af.y, hc1, cf.y);
        float2 w; w.x = hc0; w.y = hc1;
        *(float2*)&out[o] = w;
    }
}

// ---------------------------------------------------------------------------
extern "C" void kernel_launch(void* const* d_in, const int* in_sizes, int n_in,
                              void* d_out, int out_size)
{
    const float* x  = nullptr;
    const float* hp = nullptr;
    const float* Wp = nullptr;
    for (int i = 0; i < n_in; i++) {
        if      (in_sizes[i] == M_ * D_)      x  = (const float*)d_in[i];
        else if (in_sizes[i] == B_ * H_)      hp = (const float*)d_in[i];
        else if (in_sizes[i] == 3 * H_ * D_)  Wp = (const float*)d_in[i];
    }
    float* out = (float*)d_out;

    cudaFuncSetAttribute(k_gemm_mma, cudaFuncAttributeMaxDynamicSharedMemorySize, SMEM_DYN);

    k_conv_w<<<(N3H * D_) / (256 * 4), 256>>>(Wp);

    dim3 gg(NTILES, M_ / MT);          // (4, 512)
    k_gemm_mma<<<gg, 256, SMEM_DYN>>>(x);

    k_chain<<<(B_ * H_ * 32) / 256, 256>>>(hp);
    k_out<<<B_ * NCH, 128>>>(out);
}